// round 15
// baseline (speedup 1.0000x reference)
#include <cuda_runtime.h>
#include <cstdint>

// Problem constants (fixed by the dataset)
#define DD 16
#define BB 8
#define EE 2048
#define OO 2048

#define ECH    8                 // e's per chunk
#define NCHUNK (EE / ECH)        // 256
#define NTHREADS 128
#define OTILE  (NTHREADS * 4)    // 512 o's per block
#define NOT    (OO / OTILE)      // 4
#define PF     4                 // prefetch pipeline depth (one uint4 group)

#define MUL2(d_, a_, b_) \
    asm("mul.rn.f32x2 %0, %1, %2;" : "=l"(d_) : "l"(a_), "l"(b_))
#define FMA2(d_, a_, b_, c_) \
    asm("fma.rn.f32x2 %0, %1, %2, %3;" : "=l"(d_) : "l"(a_), "l"(b_), "l"(c_))
#define PACK2(d_, lo_, hi_) \
    asm("mov.b64 %0, {%1, %2};" : "=l"(d_) : "f"(lo_), "f"(hi_))
#define UNPACK2(lo_, hi_, s_) \
    asm("mov.b64 {%0, %1}, %2;" : "=f"(lo_), "=f"(hi_) : "l"(s_))

__global__ __launch_bounds__(256)
void zero_out(float* __restrict__ out) {
    out[blockIdx.x * 256 + threadIdx.x] = 0.0f;
}

__global__ __launch_bounds__(NTHREADS, 7)   // 148*7 = 1036 >= 1024 -> single wave
void delta_synapse_main(const float* __restrict__ W,
                        const float* __restrict__ signs,
                        const float* __restrict__ Xd,
                        const float* __restrict__ Wshort,
                        const float* __restrict__ dmap,
                        float* __restrict__ out) {
    // Row 8 of weffs/coef2 is all-zero: sentinel entries (el=8) contribute 0.
    __shared__ float4 weffs[ECH + 1][NTHREADS];          // 18 KB raw W (+zero row)
    __shared__ float2 coef2[(ECH + 1) * DD * BB];        // 9 KB {c,c} duplicated
    __shared__ __align__(16) uint32_t wl_off [ECH * DD + 2 * PF];
    __shared__ __align__(16) uint32_t wl_meta[ECH * DD + 2 * PF];
    __shared__ int   s_idx[ECH];
    __shared__ float s_pre[ECH];
    __shared__ int wl_n;

    const int tid   = threadIdx.x;
    const int chunk = blockIdx.x;                  // 0..255
    const int otile = blockIdx.y;                  // 0..3
    const int e0    = chunk * ECH;
    const int obase = otile * OTILE + tid * 4;

    if (tid == 0) wl_n = 0;
    if (tid < ECH) s_idx[tid] = 0;
    // zero sentinel rows (el = 8)
    weffs[ECH][tid] = make_float4(0.f, 0.f, 0.f, 0.f);
    coef2[ECH * DD * BB + tid] = make_float2(0.f, 0.f);
    __syncthreads();

    // ---- Phase 1: coef2[el][d*8+b] = {c,c}, c = Xd*(Wshort+1)  (8/thread)
    #pragma unroll
    for (int r = 0; r < (DD * BB * ECH) / NTHREADS; r++) {
        const int idx = r * NTHREADS + tid;
        const int el  = idx & (ECH - 1);
        const int g   = idx >> 3;                   // d*8 + b
        const int gi  = g * EE + e0 + el;
        const float x = Xd[gi];
        const float c = x * (Wshort[gi] + 1.0f);
        coef2[el * (DD * BB) + g] = make_float2(c, c);
    }
    __syncthreads();

    // ---- Phase 2: one thread per (el,d) pair; warp-aggregated worklist append
    {
        const int el = tid & (ECH - 1);
        const int d  = tid >> 3;                    // 0..15
        bool active = false;
        #pragma unroll
        for (int b = 0; b < BB; b++)
            if (coef2[el * (DD * BB) + d * BB + b].x != 0.0f) active = true;
        const unsigned act  = __ballot_sync(0xffffffffu, active);
        const int      lane = tid & 31;
        int base = 0;
        if (lane == 0 && act) base = atomicAdd(&wl_n, __popc(act));
        base = __shfl_sync(0xffffffffu, base, 0);
        if (active) {
            const int pos = base + __popc(act & ((1u << lane) - 1u));
            wl_off [pos] = (uint32_t)(d * EE + e0 + el) * OO;
            wl_meta[pos] = (uint32_t)(el | (d << 4));
        }
    }
    __syncthreads();

    // ---- Pad sentinels: off=0, meta el=8 -> zero rows -> contributes 0
    const int n0   = wl_n;
    const int npad = (n0 + PF - 1) & ~(PF - 1);    // multiple of 4 -> uint4 aligned
    if (tid < 2 * PF) { wl_off[n0 + tid] = 0u; wl_meta[n0 + tid] = (uint32_t)ECH; }
    __syncthreads();

    // ---- Early dmap prefetch: first group flies concurrently with Phase 3
    const float* dbase = dmap + obase;
    float4 buf[PF];
    {
        const uint4 o4 = *(const uint4*)&wl_off[0];
        buf[0] = __ldcs((const float4*)(dbase + o4.x));
        buf[1] = __ldcs((const float4*)(dbase + o4.y));
        buf[2] = __ldcs((const float4*)(dbase + o4.z));
        buf[3] = __ldcs((const float4*)(dbase + o4.w));
    }

    // ---- Phase 3a: raw W into smem; record any positive-W o per el (racy OK)
    #pragma unroll
    for (int el = 0; el < ECH; el++) {
        const float4 wv = __ldcs((const float4*)&W[(size_t)(e0 + el) * OO + obase]);
        weffs[el][tid] = wv;
        if (wv.x > 0.f || wv.y > 0.f || wv.z > 0.f || wv.w > 0.f) {
            const int c = wv.x > 0.f ? 0 : (wv.y > 0.f ? 1 : (wv.z > 0.f ? 2 : 3));
            s_idx[el] = obase + c;                  // benign race: any winner valid
        }
    }
    __syncthreads();

    // ---- Phase 3b: one scalar signs load per el (Weff == W * s_pre[e]).
    if (tid < ECH)
        s_pre[tid] = signs[(size_t)(e0 + tid) * OO + s_idx[tid]];
    __syncthreads();

    // ---- Fold s_pre into coef2 (rows 0..7; row index == r here)
    #pragma unroll
    for (int r = 0; r < ECH; r++) {
        const float s = s_pre[r];
        float2 v = coef2[r * (DD * BB) + tid];
        v.x *= s; v.y *= s;
        coef2[r * (DD * BB) + tid] = v;
    }
    __syncthreads();

    // ---- smem byte address of coef2 for raw v2.b64 loads
    uint32_t coef2_sa;
    asm("{ .reg .u64 t; cvta.to.shared.u64 t, %1; cvt.u32.u64 %0, t; }"
        : "=r"(coef2_sa) : "l"(&coef2[0]));

    unsigned long long a01[BB], a23[BB];           // acc as f32x2 pairs (32 regs)
    #pragma unroll
    for (int b = 0; b < BB; b++) { a01[b] = 0ull; a23[b] = 0ull; }

    // ---- Phase 4: PF-deep pipeline; branchless all-b f32x2 inner body.
    for (int i = 0; i < npad; i += PF) {
        const uint4 o4 = *(const uint4*)&wl_off [i + PF];  // next group's offsets
        const uint4 m4 = *(const uint4*)&wl_meta[i];       // this group's metas
        #pragma unroll
        for (int j = 0; j < PF; j++) {
            const float4 dm = buf[j];

            const uint32_t offn = (j == 0) ? o4.x : (j == 1) ? o4.y
                                : (j == 2) ? o4.z : o4.w;
            buf[j] = __ldcs((const float4*)(dbase + offn));

            const uint32_t meta = (j == 0) ? m4.x : (j == 1) ? m4.y
                                : (j == 2) ? m4.z : m4.w;
            const uint32_t el = meta & 15;          // 8 on sentinels -> zero rows
            const uint32_t d  = meta >> 4;

            const float4 wv = weffs[el][tid];
            unsigned long long w01, w23, dm01, dm23, t01, t23;
            PACK2(dm01, dm.x, dm.y); PACK2(dm23, dm.z, dm.w);
            PACK2(w01, wv.x, wv.y);  PACK2(w23, wv.z, wv.w);
            MUL2(t01, w01, dm01);    MUL2(t23, w23, dm23);

            // 8 duplicated coefficients = 64 contiguous bytes, broadcast LDS.128s
            const uint32_t ca = coef2_sa + (el * (DD * BB) + d * BB) * 8;
            unsigned long long c0, c1, c2, c3, c4, c5, c6, c7;
            asm("ld.shared.v2.b64 {%0,%1}, [%2];"    : "=l"(c0), "=l"(c1) : "r"(ca));
            asm("ld.shared.v2.b64 {%0,%1}, [%2+16];" : "=l"(c2), "=l"(c3) : "r"(ca));
            asm("ld.shared.v2.b64 {%0,%1}, [%2+32];" : "=l"(c4), "=l"(c5) : "r"(ca));
            asm("ld.shared.v2.b64 {%0,%1}, [%2+48];" : "=l"(c6), "=l"(c7) : "r"(ca));

            FMA2(a01[0], t01, c0, a01[0]); FMA2(a23[0], t23, c0, a23[0]);
            FMA2(a01[1], t01, c1, a01[1]); FMA2(a23[1], t23, c1, a23[1]);
            FMA2(a01[2], t01, c2, a01[2]); FMA2(a23[2], t23, c2, a23[2]);
            FMA2(a01[3], t01, c3, a01[3]); FMA2(a23[3], t23, c3, a23[3]);
            FMA2(a01[4], t01, c4, a01[4]); FMA2(a23[4], t23, c4, a23[4]);
            FMA2(a01[5], t01, c5, a01[5]); FMA2(a23[5], t23, c5, a23[5]);
            FMA2(a01[6], t01, c6, a01[6]); FMA2(a23[6], t23, c6, a23[6]);
            FMA2(a01[7], t01, c7, a01[7]); FMA2(a23[7], t23, c7, a23[7]);
        }
    }

    // ---- Phase 5: reduce directly into out via vector REDG (no return value).
    #pragma unroll
    for (int b = 0; b < BB; b++) {
        float x, y, z, w;
        UNPACK2(x, y, a01[b]);
        UNPACK2(z, w, a23[b]);
        float* dst = out + b * OO + obase;
        asm volatile("red.global.add.v4.f32 [%0], {%1, %2, %3, %4};"
                     :: "l"(dst), "f"(x), "f"(y), "f"(z), "f"(w)
                     : "memory");
    }
}

extern "C" void kernel_launch(void* const* d_in, const int* in_sizes, int n_in,
                              void* d_out, int out_size) {
    (void)in_sizes; (void)n_in; (void)out_size;
    const float* W      = (const float*)d_in[0];
    const float* signs  = (const float*)d_in[1];
    const float* Xd     = (const float*)d_in[2];
    const float* Wshort = (const float*)d_in[3];
    const float* dmap   = (const float*)d_in[4];
    float* out = (float*)d_out;

    zero_out<<<(BB * OO) / 256, 256>>>(out);
    dim3 grid(NCHUNK, NOT);                       // 256 x 4 = 1024 blocks, 1 wave
    delta_synapse_main<<<grid, NTHREADS>>>(W, signs, Xd, Wshort, dmap, out);
}

// round 16
// speedup vs baseline: 1.3661x; 1.3661x over previous
#include <cuda_runtime.h>
#include <cstdint>

// Problem constants (fixed by the dataset)
#define DD 16
#define BB 8
#define EE 2048
#define OO 2048

#define ECH    8                 // e's per chunk
#define NCHUNK (EE / ECH)        // 256
#define NTHREADS 128
#define OTILE  (NTHREADS * 4)    // 512 o's per block
#define NOT    (OO / OTILE)      // 4
#define PF     4                 // prefetch pipeline depth (one uint4 group)

__global__ __launch_bounds__(256)
void zero_out(float* __restrict__ out) {
    out[blockIdx.x * 256 + threadIdx.x] = 0.0f;
}

__global__ __launch_bounds__(NTHREADS, 7)   // 148*7 = 1036 >= 1024 -> single wave
void delta_synapse_main(const float* __restrict__ W,
                        const float* __restrict__ signs,
                        const float* __restrict__ Xd,
                        const float* __restrict__ Wshort,
                        const float* __restrict__ dmap,
                        float* __restrict__ out) {
    __shared__ float    coef[DD * BB][ECH];        // 4 KB: signed Xd*(Wshort+1)
    __shared__ float4   weffs[ECH][NTHREADS];      // 16 KB: raw W slice
    // Packed worklist word: ((d*EE + e) * OO) | bm.
    // off is a multiple of OO=2048, so bm (8 bits) fits in the low 11 bits.
    // Decode: bm = w & 255; el = (w >> 11) & 7; d = w >> 22; off = w & ~2047.
    __shared__ __align__(16) uint32_t wl[ECH * DD + 2 * PF];
    __shared__ int   s_idx[ECH];
    __shared__ float s_pre[ECH];
    __shared__ int wl_n;

    const int tid   = threadIdx.x;
    const int chunk = blockIdx.x;                  // 0..255
    const int otile = blockIdx.y;                  // 0..3
    const int e0    = chunk * ECH;
    const int obase = otile * OTILE + tid * 4;

    if (tid == 0) wl_n = 0;
    if (tid < ECH) s_idx[tid] = 0;
    __syncthreads();

    // ---- Phase 1: coef[d*8+b][el] = Xd * (Wshort + 1)  (1024 elems, 8/thread)
    #pragma unroll
    for (int r = 0; r < (DD * BB * ECH) / NTHREADS; r++) {
        const int idx = r * NTHREADS + tid;
        const int el  = idx & (ECH - 1);
        const int g   = idx >> 3;                   // d*8 + b
        const int gi  = g * EE + e0 + el;
        const float x = Xd[gi];
        coef[g][el] = x * (Wshort[gi] + 1.0f);
    }
    __syncthreads();

    // ---- Phase 2: one thread per (el,d) pair; warp-aggregated worklist append
    {
        const int el = tid & (ECH - 1);
        const int d  = tid >> 3;                    // 0..15
        unsigned bm = 0;
        #pragma unroll
        for (int b = 0; b < BB; b++)
            if (coef[d * BB + b][el] != 0.0f) bm |= 1u << b;
        const unsigned act  = __ballot_sync(0xffffffffu, bm != 0);
        const int      lane = tid & 31;
        int base = 0;
        if (lane == 0 && act) base = atomicAdd(&wl_n, __popc(act));
        base = __shfl_sync(0xffffffffu, base, 0);
        if (bm) {
            const int pos = base + __popc(act & ((1u << lane) - 1u));
            wl[pos] = ((uint32_t)(d * EE + e0 + el) * OO) | bm;
        }
    }
    __syncthreads();

    // ---- Pad sentinels: word 0 -> off 0, bm 0 -> skipped in the loop
    const int n0   = wl_n;
    const int npad = (n0 + PF - 1) & ~(PF - 1);    // multiple of 4 -> uint4 aligned
    if (tid < 2 * PF) wl[n0 + tid] = 0u;
    __syncthreads();

    // ---- Prologue: load first group's packed words; start their dmap LDGs
    //      (flies concurrently with the W-load phase below)
    const float* dbase = dmap + obase;
    float4 buf[PF];
    uint4  w4c = *(const uint4*)&wl[0];            // current group's words (regs)
    buf[0] = __ldcs((const float4*)(dbase + (w4c.x & ~2047u)));
    buf[1] = __ldcs((const float4*)(dbase + (w4c.y & ~2047u)));
    buf[2] = __ldcs((const float4*)(dbase + (w4c.z & ~2047u)));
    buf[3] = __ldcs((const float4*)(dbase + (w4c.w & ~2047u)));

    // ---- Phase 3a: raw W into smem; record any positive-W o per el (racy OK)
    #pragma unroll
    for (int el = 0; el < ECH; el++) {
        const float4 wv = __ldcs((const float4*)&W[(size_t)(e0 + el) * OO + obase]);
        weffs[el][tid] = wv;
        if (wv.x > 0.f || wv.y > 0.f || wv.z > 0.f || wv.w > 0.f) {
            const int c = wv.x > 0.f ? 0 : (wv.y > 0.f ? 1 : (wv.z > 0.f ? 2 : 3));
            s_idx[el] = obase + c;                  // benign race: any winner valid
        }
    }
    __syncthreads();

    // ---- Phase 3b: one scalar signs load per el (Weff == W * s_pre[e]).
    //      signs[e,o] = (W[e,o]>0) ? s_pre[e] : 0 and W>=0 => Weff == W*s_pre.
    if (tid < ECH)
        s_pre[tid] = signs[(size_t)(e0 + tid) * OO + s_idx[tid]];
    __syncthreads();

    // ---- Fold s_pre into coef so the hot loop is unchanged
    #pragma unroll
    for (int el = 0; el < ECH; el++)
        coef[tid][el] *= s_pre[el];
    __syncthreads();

    float4 acc[BB];
    #pragma unroll
    for (int b = 0; b < BB; b++) acc[b] = make_float4(0.f, 0.f, 0.f, 0.f);

    // ---- Phase 4: PF-deep pipeline. ONE LDS.128 per group (next group's
    //      packed words); the current group's words ride in registers from
    //      the previous iteration. All LDG addresses + decode are reg-only.
    for (int i = 0; i < npad; i += PF) {
        const uint4 w4n = *(const uint4*)&wl[i + PF];   // next group's words
        #pragma unroll
        for (int j = 0; j < PF; j++) {
            const float4 dm = buf[j];

            const uint32_t wn = (j == 0) ? w4n.x : (j == 1) ? w4n.y
                              : (j == 2) ? w4n.z : w4n.w;
            buf[j] = __ldcs((const float4*)(dbase + (wn & ~2047u)));

            const uint32_t w = (j == 0) ? w4c.x : (j == 1) ? w4c.y
                             : (j == 2) ? w4c.z : w4c.w;
            unsigned bm = w & 255u;
            if (bm) {                               // warp-uniform; 0 only on sentinels
                const int el = (w >> 11) & 7;
                const int d  = w >> 22;
                const float4 wv = weffs[el][tid];   // raw W; sign folded in coef
                const float t0 = wv.x * dm.x;
                const float t1 = wv.y * dm.y;
                const float t2 = wv.z * dm.z;
                const float t3 = wv.w * dm.w;
                const float* crow = &coef[d * BB][el];  // +b*ECH per batch
                while (bm) {                        // avg ~1.2 active batches
                    const int b = __ffs(bm) - 1;
                    bm &= bm - 1;
                    const float c = crow[b * ECH];  // smem broadcast
                    switch (b) {                    // static acc indexing
                    case 0: acc[0].x += t0*c; acc[0].y += t1*c; acc[0].z += t2*c; acc[0].w += t3*c; break;
                    case 1: acc[1].x += t0*c; acc[1].y += t1*c; acc[1].z += t2*c; acc[1].w += t3*c; break;
                    case 2: acc[2].x += t0*c; acc[2].y += t1*c; acc[2].z += t2*c; acc[2].w += t3*c; break;
                    case 3: acc[3].x += t0*c; acc[3].y += t1*c; acc[3].z += t2*c; acc[3].w += t3*c; break;
                    case 4: acc[4].x += t0*c; acc[4].y += t1*c; acc[4].z += t2*c; acc[4].w += t3*c; break;
                    case 5: acc[5].x += t0*c; acc[5].y += t1*c; acc[5].z += t2*c; acc[5].w += t3*c; break;
                    case 6: acc[6].x += t0*c; acc[6].y += t1*c; acc[6].z += t2*c; acc[6].w += t3*c; break;
                    default: acc[7].x += t0*c; acc[7].y += t1*c; acc[7].z += t2*c; acc[7].w += t3*c; break;
                    }
                }
            }
        }
        w4c = w4n;                                  // carry next -> current (renaming)
    }

    // ---- Phase 5: reduce directly into out via vector REDG (no return value).
    //      Per address only NCHUNK=256 adds over the whole run -> no contention.
    #pragma unroll
    for (int b = 0; b < BB; b++) {
        float* dst = out + b * OO + obase;
        asm volatile("red.global.add.v4.f32 [%0], {%1, %2, %3, %4};"
                     :: "l"(dst),
                        "f"(acc[b].x), "f"(acc[b].y), "f"(acc[b].z), "f"(acc[b].w)
                     : "memory");
    }
}

extern "C" void kernel_launch(void* const* d_in, const int* in_sizes, int n_in,
                              void* d_out, int out_size) {
    (void)in_sizes; (void)n_in; (void)out_size;
    const float* W      = (const float*)d_in[0];
    const float* signs  = (const float*)d_in[1];
    const float* Xd     = (const float*)d_in[2];
    const float* Wshort = (const float*)d_in[3];
    const float* dmap   = (const float*)d_in[4];
    float* out = (float*)d_out;

    zero_out<<<(BB * OO) / 256, 256>>>(out);
    dim3 grid(NCHUNK, NOT);                       // 256 x 4 = 1024 blocks, 1 wave
    delta_synapse_main<<<grid, NTHREADS>>>(W, signs, Xd, Wshort, dmap, out);
}